// round 4
// baseline (speedup 1.0000x reference)
#include <cuda_runtime.h>
#include <cstdint>

// Scratch (no cudaMalloc allowed)
__device__ float2 g_Mpack[64 * 32];   // g_Mpack[i*32+l] = (exp(T[i][l]), exp(T[i][l+32]))
__device__ float  g_loss[4096];
__device__ int    g_order[4096];
__device__ int    g_done;

// ---------- f32x2 packed math ----------
static __device__ __forceinline__ unsigned long long pack2f(float lo, float hi) {
    unsigned long long r;
    asm("mov.b64 %0, {%1, %2};" : "=l"(r) : "f"(lo), "f"(hi));
    return r;
}
static __device__ __forceinline__ void unpack2f(unsigned long long v, float& lo, float& hi) {
    asm("mov.b64 {%0, %1}, %2;" : "=f"(lo), "=f"(hi) : "l"(v));
}
static __device__ __forceinline__ unsigned long long ffma2(unsigned long long a,
                                                           unsigned long long b,
                                                           unsigned long long c) {
    unsigned long long d;
    asm("fma.rn.f32x2 %0, %1, %2, %3;" : "=l"(d) : "l"(a), "l"(b), "l"(c));
    return d;
}
static __device__ __forceinline__ unsigned long long fadd2(unsigned long long a,
                                                           unsigned long long b) {
    unsigned long long d;
    asm("add.rn.f32x2 %0, %1, %2;" : "=l"(d) : "l"(a), "l"(b));
    return d;
}
static __device__ __forceinline__ unsigned long long fmul2(unsigned long long a,
                                                           unsigned long long b) {
    unsigned long long d;
    asm("mul.rn.f32x2 %0, %1, %2;" : "=l"(d) : "l"(a), "l"(b));
    return d;
}

// ---------- kernel 0: fused prep (Mpack + hist + scan + scatter + counter reset) ----------
__global__ void __launch_bounds__(1024) crf_prep(const float* __restrict__ trans,
                                                 const int* __restrict__ seq_len, int B) {
    __shared__ int h[513], f[513], off[513];
    __shared__ int sc[1024];
    const int tid = threadIdx.x;

    if (tid < 513) { h[tid] = 0; f[tid] = 0; }
    for (int idx = tid; idx < 64 * 32; idx += 1024) {
        int i = idx >> 5, l = idx & 31;
        g_Mpack[idx] = make_float2(__expf(trans[i * 64 + l]),
                                   __expf(trans[i * 64 + l + 32]));
    }
    __syncthreads();

    for (int b = tid; b < B; b += 1024) {
        int s = seq_len[b];
        s = max(0, min(512, s));
        atomicAdd(&h[s], 1);
    }
    __syncthreads();

    sc[tid] = (tid < 513) ? h[512 - tid] : 0;   // reversed (descending S)
    __syncthreads();
    for (int d = 1; d < 1024; d <<= 1) {
        int v = (tid >= d) ? sc[tid - d] : 0;
        __syncthreads();
        sc[tid] += v;
        __syncthreads();
    }
    if (tid < 513) off[512 - tid] = sc[tid] - h[512 - tid];
    __syncthreads();

    for (int b = tid; b < B; b += 1024) {
        int s = seq_len[b];
        s = max(0, min(512, s));
        int pos = off[s] + atomicAdd(&f[s], 1);
        if (pos < 4096) g_order[pos] = b;
    }
    if (tid == 0) g_done = 0;
}

// ---------- kernel 1: forward pass; warp w runs sorted rows (w, B-1-w) interleaved ----------
__global__ void __launch_bounds__(128, 1) crf_forward(
    const float* __restrict__ pred,     // [B, T, 62]
    const int*   __restrict__ ref,      // [B, T]
    const int*   __restrict__ seq_len,  // [B]
    const float* __restrict__ trans,    // [64, 64]
    float* __restrict__ out,
    int B, int T)
{
    const int lane   = threadIdx.x & 31;
    const int warpIn = threadIdx.x >> 5;
    const int w      = blockIdx.x * 4 + warpIn;
    const int npairs = (B + 1) >> 1;

    __shared__ __align__(16) float aBuf[4][2][2][64];   // [warp][row][pingpong][state]
    __shared__ int s_last;
    __shared__ double s_red[128];

    // M columns (lane, lane+32) in registers
    unsigned long long Mreg[64];
#pragma unroll
    for (int i = 0; i < 64; i++)
        Mreg[i] = *reinterpret_cast<const unsigned long long*>(&g_Mpack[i * 32 + lane]);

    const float T_lo = g_Mpack[lane * 32 + 31].y;          // exp(trans[lane][63])
    const float T_hi = g_Mpack[(lane + 32) * 32 + 31].y;   // exp(trans[lane+32][63])

    if (w < npairs) {
        const int iA = w, iB = B - 1 - w;
        const bool hasB = (iB > iA);
        const int bA = g_order[iA];
        const int SA = seq_len[bA];                        // longest of the pair (sorted)
        const int bB = hasB ? g_order[iB] : bA;
        const int SB = hasB ? seq_len[bB] : 0;
        const float* pArow = pred + (size_t)bA * T * 62;
        const float* pBrow = pred + (size_t)bB * T * 62;

        float* aA[2] = { aBuf[warpIn][0][0], aBuf[warpIn][0][1] };
        float* aB[2] = { aBuf[warpIn][1][0], aBuf[warpIn][1][1] };

        // init: alpha0 = ones over 62 labels (b_s floor -1000 in C)
        aA[0][lane] = 1.0f;  aA[0][lane + 32] = (lane < 30) ? 1.0f : 0.0f;
        aB[0][lane] = 1.0f;  aB[0][lane + 32] = (lane < 30) ? 1.0f : 0.0f;
        __syncwarp();

        float CA = -1000.0f, CB = -1000.0f;
        float escA = 1.0f,   escB = 1.0f;
        float vAlo = 1.0f, vAhi = 0.0f, vBlo = 1.0f, vBhi = 0.0f;

        const int nch = (SA + 3) >> 2;                     // chunk count driven by longer row

        // double-buffered emission prefetch (4 steps per buffer), per row
        float Alo0[4], Ahi0[4], Alo1[4], Ahi1[4];
        float Blo0[4], Bhi0[4], Blo1[4], Bhi1[4];

        auto loadA = [&](float (&lo)[4], float (&hi)[4], int c) {
#pragma unroll
            for (int k = 0; k < 4; k++) {
                int u = c * 4 + k;
                if (u < SA) {
                    const float* rp = pArow + (size_t)u * 62;
                    lo[k] = rp[lane];
                    hi[k] = (lane < 30) ? rp[lane + 32] : 0.0f;
                } else { lo[k] = 0.0f; hi[k] = 0.0f; }
            }
        };
        auto loadB = [&](float (&lo)[4], float (&hi)[4], int c) {
#pragma unroll
            for (int k = 0; k < 4; k++) {
                int u = c * 4 + k;
                if (u < SB) {
                    const float* rp = pBrow + (size_t)u * 62;
                    lo[k] = rp[lane];
                    hi[k] = (lane < 30) ? rp[lane + 32] : 0.0f;
                } else { lo[k] = 0.0f; hi[k] = 0.0f; }
            }
        };

        auto matvec = [&](const float* aR, float e_lo, float e_hi,
                          float& vlo, float& vhi) {
            unsigned long long a0 = 0, a1 = 0, a2 = 0, a3 = 0,
                               a4 = 0, a5 = 0, a6 = 0, a7 = 0;
#pragma unroll
            for (int i = 0; i < 64; i += 8) {
                float4 x = *reinterpret_cast<const float4*>(&aR[i]);
                float4 y = *reinterpret_cast<const float4*>(&aR[i + 4]);
                a0 = ffma2(pack2f(x.x, x.x), Mreg[i + 0], a0);
                a1 = ffma2(pack2f(x.y, x.y), Mreg[i + 1], a1);
                a2 = ffma2(pack2f(x.z, x.z), Mreg[i + 2], a2);
                a3 = ffma2(pack2f(x.w, x.w), Mreg[i + 3], a3);
                a4 = ffma2(pack2f(y.x, y.x), Mreg[i + 4], a4);
                a5 = ffma2(pack2f(y.y, y.y), Mreg[i + 5], a5);
                a6 = ffma2(pack2f(y.z, y.z), Mreg[i + 6], a6);
                a7 = ffma2(pack2f(y.w, y.w), Mreg[i + 7], a7);
            }
            unsigned long long acc =
                fadd2(fadd2(fadd2(a0, a1), fadd2(a2, a3)),
                      fadd2(fadd2(a4, a5), fadd2(a6, a7)));
            unsigned long long v2 = fmul2(acc, pack2f(e_lo, e_hi));
            unpack2f(v2, vlo, vhi);
        };

        loadA(Alo0, Ahi0, 0);
        loadB(Blo0, Bhi0, 0);

        for (int c = 0; c < nch; c++) {
            // prefetch next chunk (one chunk of lead time to cover DRAM)
            if (c + 1 < nch)       loadA(Alo1, Ahi1, c + 1);
            if ((c + 1) * 4 < SB)  loadB(Blo1, Bhi1, c + 1);

#pragma unroll
            for (int k = 0; k < 4; k++) {
                const int u  = c * 4 + k;
                const int rd = u & 1, wr = rd ^ 1;
                if (u < SA) {
                    float sc0  = (k == 0) ? escA : 1.0f;
                    float e_lo = __expf(Alo0[k]) * sc0;
                    float e_hi = (lane < 30) ? __expf(Ahi0[k]) * sc0 : 0.0f;
                    matvec(aA[rd], e_lo, e_hi, vAlo, vAhi);
                    aA[wr][lane]      = vAlo;
                    aA[wr][lane + 32] = vAhi;
                }
                if (u < SB) {
                    float sc0  = (k == 0) ? escB : 1.0f;
                    float e_lo = __expf(Blo0[k]) * sc0;
                    float e_hi = (lane < 30) ? __expf(Bhi0[k]) * sc0 : 0.0f;
                    matvec(aB[rd], e_lo, e_hi, vBlo, vBhi);
                    aB[wr][lane]      = vBlo;
                    aB[wr][lane + 32] = vBhi;
                }
                __syncwarp();
            }

            // renormalize once per chunk (exact; scale applied lazily next chunk)
            if (c + 1 < nch) {
                float s = vAlo + vAhi;
#pragma unroll
                for (int m = 16; m >= 1; m >>= 1)
                    s += __shfl_xor_sync(0xffffffffu, s, m);
                CA += __logf(s);
                escA = __fdividef(1.0f, s);
            }
            if ((c + 1) * 4 < SB) {
                float s = vBlo + vBhi;
#pragma unroll
                for (int m = 16; m >= 1; m >>= 1)
                    s += __shfl_xor_sync(0xffffffffu, s, m);
                CB += __logf(s);
                escB = __fdividef(1.0f, s);
            }

            // rotate prefetch buffers
#pragma unroll
            for (int k = 0; k < 4; k++) {
                Alo0[k] = Alo1[k]; Ahi0[k] = Ahi1[k];
                Blo0[k] = Blo1[k]; Bhi0[k] = Bhi1[k];
            }
        }

        // finalize + gold for row A
        {
            float z = vAlo * T_lo + vAhi * T_hi;
#pragma unroll
            for (int m = 16; m >= 1; m >>= 1)
                z += __shfl_xor_sync(0xffffffffu, z, m);
            float logZ = CA + __logf(z);

            float gold = 0.0f;
            const int* refb = ref + (size_t)bA * T;
            for (int t = lane; t < SA; t += 32) {
                int rt = refb[t];
                gold += pArow[(size_t)t * 62 + rt];
                int rp = (t == 0) ? 62 : refb[t - 1];
                gold += trans[rp * 64 + rt];
            }
            if (lane == 0) gold += trans[refb[SA - 1] * 64 + 63];
#pragma unroll
            for (int m = 16; m >= 1; m >>= 1)
                gold += __shfl_xor_sync(0xffffffffu, gold, m);
            if (lane == 0 && bA < 4096) g_loss[bA] = logZ - gold;
        }

        // finalize + gold for row B
        if (hasB) {
            float z = vBlo * T_lo + vBhi * T_hi;
#pragma unroll
            for (int m = 16; m >= 1; m >>= 1)
                z += __shfl_xor_sync(0xffffffffu, z, m);
            float logZ = CB + __logf(z);

            float gold = 0.0f;
            const int* refb = ref + (size_t)bB * T;
            for (int t = lane; t < SB; t += 32) {
                int rt = refb[t];
                gold += pBrow[(size_t)t * 62 + rt];
                int rp = (t == 0) ? 62 : refb[t - 1];
                gold += trans[rp * 64 + rt];
            }
            if (lane == 0) gold += trans[refb[SB - 1] * 64 + 63];
#pragma unroll
            for (int m = 16; m >= 1; m >>= 1)
                gold += __shfl_xor_sync(0xffffffffu, gold, m);
            if (lane == 0 && bB < 4096) g_loss[bB] = logZ - gold;
        }
    }

    // ---- fused deterministic reduction: last CTA sums in fixed order ----
    __syncthreads();
    if (threadIdx.x == 0) {
        __threadfence();
        int v = atomicAdd(&g_done, 1);
        s_last = (v == gridDim.x - 1) ? 1 : 0;
    }
    __syncthreads();
    if (s_last) {
        __threadfence();
        double acc = 0.0;
        for (int i = threadIdx.x; i < B; i += 128)
            acc += (double)g_loss[i];
        s_red[threadIdx.x] = acc;
        __syncthreads();
        for (int st = 64; st >= 1; st >>= 1) {
            if (threadIdx.x < st) s_red[threadIdx.x] += s_red[threadIdx.x + st];
            __syncthreads();
        }
        if (threadIdx.x == 0) out[0] = (float)s_red[0];
    }
}

extern "C" void kernel_launch(void* const* d_in, const int* in_sizes, int n_in,
                              void* d_out, int out_size) {
    const float* pred   = (const float*)d_in[0];
    const int*   ref    = (const int*)d_in[1];
    const int*   seqlen = (const int*)d_in[2];
    const float* trans  = (const float*)d_in[3];

    int B = in_sizes[2];            // 1024
    int T = in_sizes[1] / B;        // 512

    int npairs = (B + 1) / 2;       // 512
    int ctas   = (npairs + 3) / 4;  // 128

    crf_prep<<<1, 1024>>>(trans, seqlen, B);
    crf_forward<<<ctas, 128>>>(pred, ref, seqlen, trans, (float*)d_out, B, T);
}